// round 6
// baseline (speedup 1.0000x reference)
#include <cuda_runtime.h>
#include <math.h>
#include <stdint.h>

// ---------------- problem constants ----------------
#define DIMN     1024
#define HEADS    16
#define HEAD_DIM 64
#define LAYERS   4
#define HIDDEN   4096
#define VOCAB    32000
#define BATCH    2
#define SEQ      1024
#define MTOK     (BATCH*SEQ)
#define EPS      1e-6f

// ---------------- scratch ----------------
__device__ float g_h   [MTOK*DIMN];
__device__ float g_x   [MTOK*DIMN];
__device__ float g_q   [MTOK*DIMN];
__device__ float g_k   [MTOK*DIMN];
__device__ float g_v   [MTOK*DIMN];
__device__ float g_vt  [MTOK*DIMN];
__device__ float g_y   [MTOK*DIMN];
__device__ float g_att [(size_t)BATCH*HEADS*SEQ*SEQ];
__device__ float g_gate[MTOK*HIDDEN];
__device__ float g_up  [MTOK*HIDDEN];

// ---------------- PTX helpers ----------------
__device__ __forceinline__ uint32_t smem_u32(const void* p) {
    uint32_t a;
    asm("{ .reg .u64 t; cvta.to.shared.u64 t, %1; cvt.u32.u64 %0, t; }"
        : "=r"(a) : "l"(p));
    return a;
}

__device__ __forceinline__ void ldm4(uint32_t* r, uint32_t addr) {
    asm volatile("ldmatrix.sync.aligned.m8n8.x4.shared.b16 {%0,%1,%2,%3}, [%4];"
                 : "=r"(r[0]), "=r"(r[1]), "=r"(r[2]), "=r"(r[3]) : "r"(addr));
}

__device__ __forceinline__ void mma16816(float* c, const uint32_t* a, const uint32_t* b) {
    asm volatile("mma.sync.aligned.m16n8k16.row.col.f32.bf16.bf16.f32 "
                 "{%0,%1,%2,%3}, {%4,%5,%6,%7}, {%8,%9}, {%0,%1,%2,%3};"
                 : "+f"(c[0]), "+f"(c[1]), "+f"(c[2]), "+f"(c[3])
                 : "r"(a[0]), "r"(a[1]), "r"(a[2]), "r"(a[3]),
                   "r"(b[0]), "r"(b[1]));
}

// fp32 float4 -> hi/lo bf16 quads, stored to swizzled smem.
__device__ __forceinline__ void split_store(uint32_t hi_base, uint32_t lo_base,
                                            int row, int k4, float4 f) {
    uint32_t ux = __float_as_uint(f.x), uy = __float_as_uint(f.y);
    uint32_t uz = __float_as_uint(f.z), uw = __float_as_uint(f.w);
    uint32_t h01 = __byte_perm(ux, uy, 0x7632);
    uint32_t h23 = __byte_perm(uz, uw, 0x7632);
    float lx = f.x - __uint_as_float(ux & 0xFFFF0000u);
    float ly = f.y - __uint_as_float(uy & 0xFFFF0000u);
    float lz = f.z - __uint_as_float(uz & 0xFFFF0000u);
    float lw = f.w - __uint_as_float(uw & 0xFFFF0000u);
    uint32_t l01 = __byte_perm(__float_as_uint(lx), __float_as_uint(ly), 0x7632);
    uint32_t l23 = __byte_perm(__float_as_uint(lz), __float_as_uint(lw), 0x7632);
    int chunk = k4 >> 1, half = k4 & 1;
    uint32_t off = (uint32_t)(row * 64 + ((chunk ^ ((row >> 1) & 3)) << 4) + half * 8);
    asm volatile("st.shared.v2.b32 [%0], {%1,%2};" :: "r"(hi_base + off), "r"(h01), "r"(h23));
    asm volatile("st.shared.v2.b32 [%0], {%1,%2};" :: "r"(lo_base + off), "r"(l01), "r"(l23));
}

// ================= mma.sync GEMM: C = alpha * A * B^T [+C] ================
// A row-major [M,K] k-contig, B row-major [N,K] k-contig, fp32 in/out.
// CTA tile 128 x BN, BK=32, 256 threads (8 warps, 2m x 4n).
// Split-term MMAs issued with (am,na) inner -> no same-acc back-to-back RAW.
template<int BN, bool ACCUM>
__global__ void __launch_bounds__(256, 1)
mma_gemm(const float* __restrict__ A, int lda, long sAb, long sAh,
         const float* __restrict__ B, int ldb, long sBb, long sBh,
         float*       __restrict__ C, int ldc, long sCb, long sCh,
         int K, float alpha, int hdiv)
{
    constexpr int WN    = BN / 4;
    constexpr int NA    = WN / 8;
    constexpr int NB4   = BN / 32;
    constexpr int A_LO  = 8192;
    constexpr int B_HI  = 16384;
    constexpr int BLO_D = BN * 64;
    constexpr int STAGE = 16384 + BN * 128;

    extern __shared__ char smem[];
    const uint32_t sb0 = smem_u32(smem);

    const int tid = threadIdx.x, lane = tid & 31, wid = tid >> 5;
    const int wm = wid & 1, wn = wid >> 1;

    const int z = blockIdx.z;
    A += (z / hdiv) * sAb + (z % hdiv) * sAh;
    B += (z / hdiv) * sBb + (z % hdiv) * sBh;
    C += (z / hdiv) * sCb + (z % hdiv) * sCh;
    const int m0 = blockIdx.x * 128;
    const int n0 = blockIdx.y * BN;

    uint32_t offA[4][2], offB[NA / 2][2];
    #pragma unroll
    for (int am = 0; am < 4; am++)
        #pragma unroll
        for (int kh = 0; kh < 2; kh++) {
            int mrow  = wm * 64 + am * 16 + (lane & 7) + ((lane >> 3) & 1) * 8;
            int chunk = kh * 2 + ((lane >> 4) & 1);
            offA[am][kh] = (uint32_t)(mrow * 64 + ((chunk ^ ((mrow >> 1) & 3)) << 4));
        }
    #pragma unroll
    for (int p = 0; p < NA / 2; p++)
        #pragma unroll
        for (int kh = 0; kh < 2; kh++) {
            int nrow  = wn * WN + p * 16 + (lane & 7) + ((lane >> 4) & 1) * 8;
            int chunk = kh * 2 + ((lane >> 3) & 1);
            offB[p][kh] = (uint32_t)(B_HI + nrow * 64 + ((chunk ^ ((nrow >> 1) & 3)) << 4));
        }

    float acc[4][NA][4];
    #pragma unroll
    for (int i = 0; i < 4; i++)
        #pragma unroll
        for (int j = 0; j < NA; j++)
            #pragma unroll
            for (int e = 0; e < 4; e++) acc[i][j][e] = 0.0f;

    float4 pa[4], pb[NB4];
    auto LOADG = [&](int k0) {
        #pragma unroll
        for (int i = 0; i < 4; i++) {
            int idx = i * 256 + tid, row = idx >> 3, k4 = idx & 7;
            pa[i] = *(const float4*)&A[(long)(m0 + row) * lda + k0 + k4 * 4];
        }
        #pragma unroll
        for (int i = 0; i < NB4; i++) {
            int idx = i * 256 + tid, row = idx >> 3, k4 = idx & 7;
            pb[i] = *(const float4*)&B[(long)(n0 + row) * ldb + k0 + k4 * 4];
        }
    };
    auto STORES = [&](uint32_t base) {
        #pragma unroll
        for (int i = 0; i < 4; i++) {
            int idx = i * 256 + tid, row = idx >> 3, k4 = idx & 7;
            split_store(base, base + A_LO, row, k4, pa[i]);
        }
        #pragma unroll
        for (int i = 0; i < NB4; i++) {
            int idx = i * 256 + tid, row = idx >> 3, k4 = idx & 7;
            split_store(base + B_HI, base + B_HI + BLO_D, row, k4, pb[i]);
        }
    };

    const int nk = K >> 5;
    LOADG(0);
    STORES(sb0);
    __syncthreads();

    for (int t = 0; t < nk; t++) {
        const uint32_t sb = sb0 + (uint32_t)(t & 1) * STAGE;
        if (t + 1 < nk) LOADG((t + 1) * 32);

        #pragma unroll
        for (int kh = 0; kh < 2; kh++) {
            uint32_t ah[4][4], al[4][4];
            #pragma unroll
            for (int am = 0; am < 4; am++) {
                ldm4(ah[am], sb + offA[am][kh]);
                ldm4(al[am], sb + offA[am][kh] + A_LO);
            }
            uint32_t bh[NA / 2][4], bl[NA / 2][4];
            #pragma unroll
            for (int p = 0; p < NA / 2; p++) {
                ldm4(bh[p], sb + offB[p][kh]);
                ldm4(bl[p], sb + offB[p][kh] + BLO_D);
            }
            // term 1: hi*hi — all (am,na) independent accumulators
            #pragma unroll
            for (int am = 0; am < 4; am++)
                #pragma unroll
                for (int na = 0; na < NA; na++)
                    mma16816(acc[am][na], ah[am], &bh[na >> 1][(na & 1) * 2]);
            // term 2: hi*lo
            #pragma unroll
            for (int am = 0; am < 4; am++)
                #pragma unroll
                for (int na = 0; na < NA; na++)
                    mma16816(acc[am][na], ah[am], &bl[na >> 1][(na & 1) * 2]);
            // term 3: lo*hi
            #pragma unroll
            for (int am = 0; am < 4; am++)
                #pragma unroll
                for (int na = 0; na < NA; na++)
                    mma16816(acc[am][na], al[am], &bh[na >> 1][(na & 1) * 2]);
        }

        if (t + 1 < nk) STORES(sb0 + (uint32_t)((t & 1) ^ 1) * STAGE);
        __syncthreads();
    }

    #pragma unroll
    for (int am = 0; am < 4; am++)
        #pragma unroll
        for (int na = 0; na < NA; na++) {
            int row = m0 + wm * 64 + am * 16 + (lane >> 2);
            int col = n0 + wn * WN + na * 8 + (lane & 3) * 2;
            float* base0 = &C[(long)row * ldc + col];
            float* base1 = &C[(long)(row + 8) * ldc + col];
            float2 r0 = { alpha * acc[am][na][0], alpha * acc[am][na][1] };
            float2 r1 = { alpha * acc[am][na][2], alpha * acc[am][na][3] };
            if (ACCUM) {
                float2 o0 = *(float2*)base0, o1 = *(float2*)base1;
                r0.x += o0.x; r0.y += o0.y; r1.x += o1.x; r1.y += o1.y;
            }
            *(float2*)base0 = r0;
            *(float2*)base1 = r1;
        }
}

// ---------------- elementwise kernels ----------------
__global__ void embed_kernel(const int* __restrict__ tokens,
                             const float* __restrict__ embed,
                             float* __restrict__ h)
{
    int row = blockIdx.x;
    int tok = tokens[row];
    ((float4*)(h + (long)row * DIMN))[threadIdx.x] =
        ((const float4*)(embed + (long)tok * DIMN))[threadIdx.x];
}

__global__ void rmsnorm_kernel(const float* __restrict__ x,
                               const float* __restrict__ w,
                               float* __restrict__ out)
{
    int row = blockIdx.x;
    float4 v = ((const float4*)(x + (long)row * DIMN))[threadIdx.x];
    float ss = v.x*v.x + v.y*v.y + v.z*v.z + v.w*v.w;
    __shared__ float red[8];
    #pragma unroll
    for (int o = 16; o > 0; o >>= 1) ss += __shfl_xor_sync(0xFFFFFFFFu, ss, o);
    if ((threadIdx.x & 31) == 0) red[threadIdx.x >> 5] = ss;
    __syncthreads();
    if (threadIdx.x < 8) {
        float s = red[threadIdx.x];
        #pragma unroll
        for (int o = 4; o > 0; o >>= 1) s += __shfl_xor_sync(0xFFu, s, o);
        if (threadIdx.x == 0) red[0] = s;
    }
    __syncthreads();
    float scale = rsqrtf(red[0] * (1.0f / DIMN) + EPS);
    float4 wv = ((const float4*)w)[threadIdx.x];
    float4 o4 = { v.x*scale*wv.x, v.y*scale*wv.y, v.z*scale*wv.z, v.w*scale*wv.w };
    ((float4*)(out + (long)row * DIMN))[threadIdx.x] = o4;
}

__global__ void softmax_kernel(float* __restrict__ att)
{
    long row = blockIdx.x;
    float4* p = (float4*)(att + row * (long)SEQ);
    float4 v = p[threadIdx.x];
    __shared__ float red[8];
    float mx = fmaxf(fmaxf(v.x, v.y), fmaxf(v.z, v.w));
    #pragma unroll
    for (int o = 16; o > 0; o >>= 1) mx = fmaxf(mx, __shfl_xor_sync(0xFFFFFFFFu, mx, o));
    if ((threadIdx.x & 31) == 0) red[threadIdx.x >> 5] = mx;
    __syncthreads();
    if (threadIdx.x < 8) {
        float s = red[threadIdx.x];
        #pragma unroll
        for (int o = 4; o > 0; o >>= 1) s = fmaxf(s, __shfl_xor_sync(0xFFu, s, o));
        if (threadIdx.x == 0) red[0] = s;
    }
    __syncthreads();
    mx = red[0];
    __syncthreads();
    v.x = expf(v.x - mx); v.y = expf(v.y - mx);
    v.z = expf(v.z - mx); v.w = expf(v.w - mx);
    float sum = v.x + v.y + v.z + v.w;
    #pragma unroll
    for (int o = 16; o > 0; o >>= 1) sum += __shfl_xor_sync(0xFFFFFFFFu, sum, o);
    if ((threadIdx.x & 31) == 0) red[threadIdx.x >> 5] = sum;
    __syncthreads();
    if (threadIdx.x < 8) {
        float s = red[threadIdx.x];
        #pragma unroll
        for (int o = 4; o > 0; o >>= 1) s += __shfl_xor_sync(0xFFu, s, o);
        if (threadIdx.x == 0) red[0] = s;
    }
    __syncthreads();
    float inv = 1.0f / red[0];
    v.x *= inv; v.y *= inv; v.z *= inv; v.w *= inv;
    p[threadIdx.x] = v;
}

__global__ void silu_mul_kernel(float4* __restrict__ g, const float4* __restrict__ u)
{
    long i = (long)blockIdx.x * blockDim.x + threadIdx.x;
    float4 gv = g[i], uv = u[i];
    gv.x = gv.x / (1.0f + expf(-gv.x)) * uv.x;
    gv.y = gv.y / (1.0f + expf(-gv.y)) * uv.y;
    gv.z = gv.z / (1.0f + expf(-gv.z)) * uv.z;
    gv.w = gv.w / (1.0f + expf(-gv.w)) * uv.w;
    g[i] = gv;
}

// vt[(b*H+h)][d][s] = v[b*SEQ+s][h*64+d]
__global__ void transpose_v_kernel(const float* __restrict__ v, float* __restrict__ vt)
{
    __shared__ float t[32][33];
    int bh = blockIdx.z, b = bh >> 4, hh = bh & 15;
    int s0 = blockIdx.x * 32, d0 = blockIdx.y * 32;
    int tx = threadIdx.x, ty = threadIdx.y;    // 32 x 8
    #pragma unroll
    for (int j = 0; j < 32; j += 8)
        t[ty + j][tx] = v[(long)(b * SEQ + s0 + ty + j) * DIMN + hh * HEAD_DIM + d0 + tx];
    __syncthreads();
    #pragma unroll
    for (int j = 0; j < 32; j += 8)
        vt[((long)bh * HEAD_DIM + d0 + ty + j) * SEQ + s0 + tx] = t[tx][ty + j];
}

// ---------------- launcher ----------------
extern "C" void kernel_launch(void* const* d_in, const int* in_sizes, int n_in,
                              void* d_out, int out_size)
{
    const int*   tokens  = (const int*)  d_in[0];
    const float* embed   = (const float*)d_in[1];
    const float* Wq      = (const float*)d_in[2];
    const float* Wk      = (const float*)d_in[3];
    const float* Wv      = (const float*)d_in[4];
    const float* Wo      = (const float*)d_in[5];
    const float* Wg      = (const float*)d_in[6];
    const float* Wu      = (const float*)d_in[7];
    const float* Wd      = (const float*)d_in[8];
    const float* ln1     = (const float*)d_in[9];
    const float* ln2     = (const float*)d_in[10];
    const float* norm_w  = (const float*)d_in[11];
    const float* lm_head = (const float*)d_in[12];
    float* out = (float*)d_out;

    float *h, *x, *q, *k, *v, *vt, *y, *att, *gate, *up;
    cudaGetSymbolAddress((void**)&h,    g_h);
    cudaGetSymbolAddress((void**)&x,    g_x);
    cudaGetSymbolAddress((void**)&q,    g_q);
    cudaGetSymbolAddress((void**)&k,    g_k);
    cudaGetSymbolAddress((void**)&v,    g_v);
    cudaGetSymbolAddress((void**)&vt,   g_vt);
    cudaGetSymbolAddress((void**)&y,    g_y);
    cudaGetSymbolAddress((void**)&att,  g_att);
    cudaGetSymbolAddress((void**)&gate, g_gate);
    cudaGetSymbolAddress((void**)&up,   g_up);

    const int DYN128 = 2 * (16384 + 128 * 128);   // 65536
    const int DYN64  = 2 * (16384 + 64 * 128);    // 49152
    cudaFuncSetAttribute(mma_gemm<128, false>, cudaFuncAttributeMaxDynamicSharedMemorySize, DYN128);
    cudaFuncSetAttribute(mma_gemm<128, true>,  cudaFuncAttributeMaxDynamicSharedMemorySize, DYN128);
    cudaFuncSetAttribute(mma_gemm<64,  false>, cudaFuncAttributeMaxDynamicSharedMemorySize, DYN64);

    const float scale = 1.0f / sqrtf((float)HEAD_DIM);

    embed_kernel<<<MTOK, 256>>>(tokens, embed, h);

    dim3 gProj (MTOK / 128, DIMN / 128, 1);            // 16 x 8
    dim3 gFfn  (MTOK / 128, HIDDEN / 128, 1);          // 16 x 32
    dim3 gScore(SEQ / 128, SEQ / 128, BATCH * HEADS);  // 8 x 8 x 32
    dim3 gAV   (SEQ / 128, 1, BATCH * HEADS);          // 8 x 1 x 32
    dim3 gHead (MTOK / 128, VOCAB / 128, 1);           // 16 x 250
    dim3 gTr   (SEQ / 32, HEAD_DIM / 32, BATCH * HEADS);

    for (int l = 0; l < LAYERS; l++) {
        const float* wq = Wq + (long)l * DIMN * DIMN;
        const float* wk = Wk + (long)l * DIMN * DIMN;
        const float* wv = Wv + (long)l * DIMN * DIMN;
        const float* wo = Wo + (long)l * DIMN * DIMN;
        const float* wg = Wg + (long)l * HIDDEN * DIMN;
        const float* wu = Wu + (long)l * HIDDEN * DIMN;
        const float* wd = Wd + (long)l * DIMN * HIDDEN;

        rmsnorm_kernel<<<MTOK, 256>>>(h, ln1 + (long)l * DIMN, x);

        mma_gemm<128, false><<<gProj, 256, DYN128>>>(x, DIMN, 0, 0, wq, DIMN, 0, 0,
                                                     q, DIMN, 0, 0, DIMN, 1.0f, 1);
        mma_gemm<128, false><<<gProj, 256, DYN128>>>(x, DIMN, 0, 0, wk, DIMN, 0, 0,
                                                     k, DIMN, 0, 0, DIMN, 1.0f, 1);
        mma_gemm<128, false><<<gProj, 256, DYN128>>>(x, DIMN, 0, 0, wv, DIMN, 0, 0,
                                                     v, DIMN, 0, 0, DIMN, 1.0f, 1);

        // att = scale * q k^T  (batched over b,h; K = HEAD_DIM)
        mma_gemm<128, false><<<gScore, 256, DYN128>>>(
            q, DIMN, (long)SEQ * DIMN, HEAD_DIM,
            k, DIMN, (long)SEQ * DIMN, HEAD_DIM,
            att, SEQ, (long)HEADS * SEQ * SEQ, (long)SEQ * SEQ,
            HEAD_DIM, scale, HEADS);

        softmax_kernel<<<BATCH * HEADS * SEQ, 256>>>(att);

        transpose_v_kernel<<<gTr, dim3(32, 8)>>>(v, vt);

        // y = att @ v  (NT with vt[b,h][d][s]; N = HEAD_DIM, K = SEQ)
        mma_gemm<64, false><<<gAV, 256, DYN64>>>(
            att, SEQ, (long)HEADS * SEQ * SEQ, (long)SEQ * SEQ,
            vt, SEQ, (long)HEADS * HEAD_DIM * SEQ, (long)HEAD_DIM * SEQ,
            y, DIMN, (long)SEQ * DIMN, HEAD_DIM,
            SEQ, 1.0f, HEADS);

        // h += y @ Wo^T
        mma_gemm<128, true><<<gProj, 256, DYN128>>>(y, DIMN, 0, 0, wo, DIMN, 0, 0,
                                                    h, DIMN, 0, 0, DIMN, 1.0f, 1);

        rmsnorm_kernel<<<MTOK, 256>>>(h, ln2 + (long)l * DIMN, x);

        mma_gemm<128, false><<<gFfn, 256, DYN128>>>(x, DIMN, 0, 0, wg, DIMN, 0, 0,
                                                    gate, HIDDEN, 0, 0, DIMN, 1.0f, 1);
        mma_gemm<128, false><<<gFfn, 256, DYN128>>>(x, DIMN, 0, 0, wu, DIMN, 0, 0,
                                                    up, HIDDEN, 0, 0, DIMN, 1.0f, 1);

        silu_mul_kernel<<<(MTOK * (long)HIDDEN / 4) / 256, 256>>>((float4*)gate, (const float4*)up);

        // h += gate @ Wd^T
        mma_gemm<128, true><<<gProj, 256, DYN128>>>(gate, HIDDEN, 0, 0, wd, HIDDEN, 0, 0,
                                                    h, DIMN, 0, 0, HIDDEN, 1.0f, 1);
    }

    rmsnorm_kernel<<<MTOK, 256>>>(h, norm_w, x);
    mma_gemm<128, false><<<gHead, 256, DYN128>>>(x, DIMN, 0, 0, lm_head, DIMN, 0, 0,
                                                 out, VOCAB, 0, 0, DIMN, 1.0f, 1);
}

// round 7
// speedup vs baseline: 1.4705x; 1.4705x over previous
#include <cuda_runtime.h>
#include <math.h>
#include <stdint.h>

// ---------------- problem constants ----------------
#define DIMN     1024
#define HEADS    16
#define HEAD_DIM 64
#define LAYERS   4
#define HIDDEN   4096
#define VOCAB    32000
#define BATCH    2
#define SEQ      1024
#define MTOK     (BATCH*SEQ)
#define EPS      1e-6f

// ---------------- scratch ----------------
__device__ float g_h   [MTOK*DIMN];
__device__ float g_x   [MTOK*DIMN];
__device__ float g_q   [MTOK*DIMN];
__device__ float g_k   [MTOK*DIMN];
__device__ float g_v   [MTOK*DIMN];
__device__ float g_vt  [MTOK*DIMN];
__device__ float g_y   [MTOK*DIMN];
__device__ float g_att [(size_t)BATCH*HEADS*SEQ*SEQ];
__device__ float g_gate[MTOK*HIDDEN];
__device__ float g_up  [MTOK*HIDDEN];

// ---------------- PTX helpers ----------------
__device__ __forceinline__ uint32_t smem_u32(const void* p) {
    uint32_t a;
    asm("{ .reg .u64 t; cvta.to.shared.u64 t, %1; cvt.u32.u64 %0, t; }"
        : "=r"(a) : "l"(p));
    return a;
}

__device__ __forceinline__ void ldm4(uint32_t* r, uint32_t addr) {
    asm volatile("ldmatrix.sync.aligned.m8n8.x4.shared.b16 {%0,%1,%2,%3}, [%4];"
                 : "=r"(r[0]), "=r"(r[1]), "=r"(r[2]), "=r"(r[3]) : "r"(addr));
}

__device__ __forceinline__ void mma16816(float* c, const uint32_t* a, const uint32_t* b) {
    asm volatile("mma.sync.aligned.m16n8k16.row.col.f32.bf16.bf16.f32 "
                 "{%0,%1,%2,%3}, {%4,%5,%6,%7}, {%8,%9}, {%0,%1,%2,%3};"
                 : "+f"(c[0]), "+f"(c[1]), "+f"(c[2]), "+f"(c[3])
                 : "r"(a[0]), "r"(a[1]), "r"(a[2]), "r"(a[3]),
                   "r"(b[0]), "r"(b[1]));
}

// fp32 float4 -> hi/lo bf16 quads, stored to swizzled smem.
__device__ __forceinline__ void split_store(uint32_t hi_base, uint32_t lo_base,
                                            int row, int k4, float4 f) {
    uint32_t ux = __float_as_uint(f.x), uy = __float_as_uint(f.y);
    uint32_t uz = __float_as_uint(f.z), uw = __float_as_uint(f.w);
    uint32_t h01 = __byte_perm(ux, uy, 0x7632);
    uint32_t h23 = __byte_perm(uz, uw, 0x7632);
    float lx = f.x - __uint_as_float(ux & 0xFFFF0000u);
    float ly = f.y - __uint_as_float(uy & 0xFFFF0000u);
    float lz = f.z - __uint_as_float(uz & 0xFFFF0000u);
    float lw = f.w - __uint_as_float(uw & 0xFFFF0000u);
    uint32_t l01 = __byte_perm(__float_as_uint(lx), __float_as_uint(ly), 0x7632);
    uint32_t l23 = __byte_perm(__float_as_uint(lz), __float_as_uint(lw), 0x7632);
    int chunk = k4 >> 1, half = k4 & 1;
    uint32_t off = (uint32_t)(row * 64 + ((chunk ^ ((row >> 1) & 3)) << 4) + half * 8);
    asm volatile("st.shared.v2.b32 [%0], {%1,%2};" :: "r"(hi_base + off), "r"(h01), "r"(h23));
    asm volatile("st.shared.v2.b32 [%0], {%1,%2};" :: "r"(lo_base + off), "r"(l01), "r"(l23));
}

// ================= mma.sync GEMM: C = alpha * A * B^T [+C] ================
// A row-major [M,K] k-contig, B row-major [N,K] k-contig, fp32 in/out.
// CTA tile 128 x 64, BK=32, 256 threads (8 warps, 2m x 4n), 2 CTAs/SM.
// Structure identical to the validated R4 kernel (BN=64 instantiation).
template<bool ACCUM>
__global__ void __launch_bounds__(256, 2)
mma_gemm(const float* __restrict__ A, int lda, long sAb, long sAh,
         const float* __restrict__ B, int ldb, long sBb, long sBh,
         float*       __restrict__ C, int ldc, long sCb, long sCh,
         int K, float alpha, int hdiv)
{
    constexpr int BN    = 64;
    constexpr int WN    = BN / 4;           // 16
    constexpr int NA    = WN / 8;           // 2
    constexpr int NB4   = BN / 32;          // 2
    constexpr int A_LO  = 8192;
    constexpr int B_HI  = 16384;
    constexpr int BLO_D = BN * 64;          // 4096
    constexpr int STAGE = 16384 + BN * 128; // 24576

    extern __shared__ char smem[];
    const uint32_t sb0 = smem_u32(smem);

    const int tid = threadIdx.x, lane = tid & 31, wid = tid >> 5;
    const int wm = wid & 1, wn = wid >> 1;

    const int z = blockIdx.z;
    A += (z / hdiv) * sAb + (z % hdiv) * sAh;
    B += (z / hdiv) * sBb + (z % hdiv) * sBh;
    C += (z / hdiv) * sCb + (z % hdiv) * sCh;
    const int m0 = blockIdx.x * 128;
    const int n0 = blockIdx.y * BN;

    uint32_t offA[4][2], offB[NA / 2][2];
    #pragma unroll
    for (int am = 0; am < 4; am++)
        #pragma unroll
        for (int kh = 0; kh < 2; kh++) {
            int mrow  = wm * 64 + am * 16 + (lane & 7) + ((lane >> 3) & 1) * 8;
            int chunk = kh * 2 + ((lane >> 4) & 1);
            offA[am][kh] = (uint32_t)(mrow * 64 + ((chunk ^ ((mrow >> 1) & 3)) << 4));
        }
    #pragma unroll
    for (int p = 0; p < NA / 2; p++)
        #pragma unroll
        for (int kh = 0; kh < 2; kh++) {
            int nrow  = wn * WN + p * 16 + (lane & 7) + ((lane >> 4) & 1) * 8;
            int chunk = kh * 2 + ((lane >> 3) & 1);
            offB[p][kh] = (uint32_t)(B_HI + nrow * 64 + ((chunk ^ ((nrow >> 1) & 3)) << 4));
        }

    float acc[4][NA][4];
    #pragma unroll
    for (int i = 0; i < 4; i++)
        #pragma unroll
        for (int j = 0; j < NA; j++)
            #pragma unroll
            for (int e = 0; e < 4; e++) acc[i][j][e] = 0.0f;

    float4 pa[4], pb[NB4];
    auto LOADG = [&](int k0) {
        #pragma unroll
        for (int i = 0; i < 4; i++) {
            int idx = i * 256 + tid, row = idx >> 3, k4 = idx & 7;
            pa[i] = *(const float4*)&A[(long)(m0 + row) * lda + k0 + k4 * 4];
        }
        #pragma unroll
        for (int i = 0; i < NB4; i++) {
            int idx = i * 256 + tid, row = idx >> 3, k4 = idx & 7;
            pb[i] = *(const float4*)&B[(long)(n0 + row) * ldb + k0 + k4 * 4];
        }
    };
    auto STORES = [&](uint32_t base) {
        #pragma unroll
        for (int i = 0; i < 4; i++) {
            int idx = i * 256 + tid, row = idx >> 3, k4 = idx & 7;
            split_store(base, base + A_LO, row, k4, pa[i]);
        }
        #pragma unroll
        for (int i = 0; i < NB4; i++) {
            int idx = i * 256 + tid, row = idx >> 3, k4 = idx & 7;
            split_store(base + B_HI, base + B_HI + BLO_D, row, k4, pb[i]);
        }
    };

    const int nk = K >> 5;
    LOADG(0);
    STORES(sb0);
    __syncthreads();

    for (int t = 0; t < nk; t++) {
        const uint32_t sb = sb0 + (uint32_t)(t & 1) * STAGE;
        if (t + 1 < nk) LOADG((t + 1) * 32);

        #pragma unroll
        for (int kh = 0; kh < 2; kh++) {
            uint32_t ah[4][4], al[4][4];
            #pragma unroll
            for (int am = 0; am < 4; am++) {
                ldm4(ah[am], sb + offA[am][kh]);
                ldm4(al[am], sb + offA[am][kh] + A_LO);
            }
            uint32_t bh[NA / 2][4], bl[NA / 2][4];
            #pragma unroll
            for (int p = 0; p < NA / 2; p++) {
                ldm4(bh[p], sb + offB[p][kh]);
                ldm4(bl[p], sb + offB[p][kh] + BLO_D);
            }
            #pragma unroll
            for (int am = 0; am < 4; am++)
                #pragma unroll
                for (int na = 0; na < NA; na++) {
                    const uint32_t* bhp = &bh[na >> 1][(na & 1) * 2];
                    const uint32_t* blp = &bl[na >> 1][(na & 1) * 2];
                    mma16816(acc[am][na], ah[am], bhp);
                    mma16816(acc[am][na], ah[am], blp);
                    mma16816(acc[am][na], al[am], bhp);
                }
        }

        if (t + 1 < nk) STORES(sb0 + (uint32_t)((t & 1) ^ 1) * STAGE);
        __syncthreads();
    }

    #pragma unroll
    for (int am = 0; am < 4; am++)
        #pragma unroll
        for (int na = 0; na < NA; na++) {
            int row = m0 + wm * 64 + am * 16 + (lane >> 2);
            int col = n0 + wn * WN + na * 8 + (lane & 3) * 2;
            float* base0 = &C[(long)row * ldc + col];
            float* base1 = &C[(long)(row + 8) * ldc + col];
            float2 r0 = { alpha * acc[am][na][0], alpha * acc[am][na][1] };
            float2 r1 = { alpha * acc[am][na][2], alpha * acc[am][na][3] };
            if (ACCUM) {
                float2 o0 = *(float2*)base0, o1 = *(float2*)base1;
                r0.x += o0.x; r0.y += o0.y; r1.x += o1.x; r1.y += o1.y;
            }
            *(float2*)base0 = r0;
            *(float2*)base1 = r1;
        }
}

// ---------------- elementwise kernels ----------------
__global__ void embed_kernel(const int* __restrict__ tokens,
                             const float* __restrict__ embed,
                             float* __restrict__ h)
{
    int row = blockIdx.x;
    int tok = tokens[row];
    ((float4*)(h + (long)row * DIMN))[threadIdx.x] =
        ((const float4*)(embed + (long)tok * DIMN))[threadIdx.x];
}

__global__ void rmsnorm_kernel(const float* __restrict__ x,
                               const float* __restrict__ w,
                               float* __restrict__ out)
{
    int row = blockIdx.x;
    float4 v = ((const float4*)(x + (long)row * DIMN))[threadIdx.x];
    float ss = v.x*v.x + v.y*v.y + v.z*v.z + v.w*v.w;
    __shared__ float red[8];
    #pragma unroll
    for (int o = 16; o > 0; o >>= 1) ss += __shfl_xor_sync(0xFFFFFFFFu, ss, o);
    if ((threadIdx.x & 31) == 0) red[threadIdx.x >> 5] = ss;
    __syncthreads();
    if (threadIdx.x < 8) {
        float s = red[threadIdx.x];
        #pragma unroll
        for (int o = 4; o > 0; o >>= 1) s += __shfl_xor_sync(0xFFu, s, o);
        if (threadIdx.x == 0) red[0] = s;
    }
    __syncthreads();
    float scale = rsqrtf(red[0] * (1.0f / DIMN) + EPS);
    float4 wv = ((const float4*)w)[threadIdx.x];
    float4 o4 = { v.x*scale*wv.x, v.y*scale*wv.y, v.z*scale*wv.z, v.w*scale*wv.w };
    ((float4*)(out + (long)row * DIMN))[threadIdx.x] = o4;
}

__global__ void softmax_kernel(float* __restrict__ att)
{
    long row = blockIdx.x;
    float4* p = (float4*)(att + row * (long)SEQ);
    float4 v = p[threadIdx.x];
    __shared__ float red[8];
    float mx = fmaxf(fmaxf(v.x, v.y), fmaxf(v.z, v.w));
    #pragma unroll
    for (int o = 16; o > 0; o >>= 1) mx = fmaxf(mx, __shfl_xor_sync(0xFFFFFFFFu, mx, o));
    if ((threadIdx.x & 31) == 0) red[threadIdx.x >> 5] = mx;
    __syncthreads();
    if (threadIdx.x < 8) {
        float s = red[threadIdx.x];
        #pragma unroll
        for (int o = 4; o > 0; o >>= 1) s = fmaxf(s, __shfl_xor_sync(0xFFu, s, o));
        if (threadIdx.x == 0) red[0] = s;
    }
    __syncthreads();
    mx = red[0];
    __syncthreads();
    v.x = expf(v.x - mx); v.y = expf(v.y - mx);
    v.z = expf(v.z - mx); v.w = expf(v.w - mx);
    float sum = v.x + v.y + v.z + v.w;
    #pragma unroll
    for (int o = 16; o > 0; o >>= 1) sum += __shfl_xor_sync(0xFFFFFFFFu, sum, o);
    if ((threadIdx.x & 31) == 0) red[threadIdx.x >> 5] = sum;
    __syncthreads();
    if (threadIdx.x < 8) {
        float s = red[threadIdx.x];
        #pragma unroll
        for (int o = 4; o > 0; o >>= 1) s += __shfl_xor_sync(0xFFu, s, o);
        if (threadIdx.x == 0) red[0] = s;
    }
    __syncthreads();
    float inv = 1.0f / red[0];
    v.x *= inv; v.y *= inv; v.z *= inv; v.w *= inv;
    p[threadIdx.x] = v;
}

__global__ void silu_mul_kernel(float4* __restrict__ g, const float4* __restrict__ u)
{
    long i = (long)blockIdx.x * blockDim.x + threadIdx.x;
    float4 gv = g[i], uv = u[i];
    gv.x = gv.x / (1.0f + expf(-gv.x)) * uv.x;
    gv.y = gv.y / (1.0f + expf(-gv.y)) * uv.y;
    gv.z = gv.z / (1.0f + expf(-gv.z)) * uv.z;
    gv.w = gv.w / (1.0f + expf(-gv.w)) * uv.w;
    g[i] = gv;
}

// vt[(b*H+h)][d][s] = v[b*SEQ+s][h*64+d]
__global__ void transpose_v_kernel(const float* __restrict__ v, float* __restrict__ vt)
{
    __shared__ float t[32][33];
    int bh = blockIdx.z, b = bh >> 4, hh = bh & 15;
    int s0 = blockIdx.x * 32, d0 = blockIdx.y * 32;
    int tx = threadIdx.x, ty = threadIdx.y;    // 32 x 8
    #pragma unroll
    for (int j = 0; j < 32; j += 8)
        t[ty + j][tx] = v[(long)(b * SEQ + s0 + ty + j) * DIMN + hh * HEAD_DIM + d0 + tx];
    __syncthreads();
    #pragma unroll
    for (int j = 0; j < 32; j += 8)
        vt[((long)bh * HEAD_DIM + d0 + ty + j) * SEQ + s0 + tx] = t[tx][ty + j];
}

// ---------------- launcher ----------------
extern "C" void kernel_launch(void* const* d_in, const int* in_sizes, int n_in,
                              void* d_out, int out_size)
{
    const int*   tokens  = (const int*)  d_in[0];
    const float* embed   = (const float*)d_in[1];
    const float* Wq      = (const float*)d_in[2];
    const float* Wk      = (const float*)d_in[3];
    const float* Wv      = (const float*)d_in[4];
    const float* Wo      = (const float*)d_in[5];
    const float* Wg      = (const float*)d_in[6];
    const float* Wu      = (const float*)d_in[7];
    const float* Wd      = (const float*)d_in[8];
    const float* ln1     = (const float*)d_in[9];
    const float* ln2     = (const float*)d_in[10];
    const float* norm_w  = (const float*)d_in[11];
    const float* lm_head = (const float*)d_in[12];
    float* out = (float*)d_out;

    float *h, *x, *q, *k, *v, *vt, *y, *att, *gate, *up;
    cudaGetSymbolAddress((void**)&h,    g_h);
    cudaGetSymbolAddress((void**)&x,    g_x);
    cudaGetSymbolAddress((void**)&q,    g_q);
    cudaGetSymbolAddress((void**)&k,    g_k);
    cudaGetSymbolAddress((void**)&v,    g_v);
    cudaGetSymbolAddress((void**)&vt,   g_vt);
    cudaGetSymbolAddress((void**)&y,    g_y);
    cudaGetSymbolAddress((void**)&att,  g_att);
    cudaGetSymbolAddress((void**)&gate, g_gate);
    cudaGetSymbolAddress((void**)&up,   g_up);

    const int DYN = 2 * (16384 + 64 * 128);    // 49152 (2 stages, BN=64)
    cudaFuncSetAttribute(mma_gemm<false>, cudaFuncAttributeMaxDynamicSharedMemorySize, DYN);
    cudaFuncSetAttribute(mma_gemm<true>,  cudaFuncAttributeMaxDynamicSharedMemorySize, DYN);

    const float scale = 1.0f / sqrtf((float)HEAD_DIM);

    embed_kernel<<<MTOK, 256>>>(tokens, embed, h);

    // grid: x = m-tiles (fast -> B-panel reuse in L2 across a wave), y = n-tiles
    dim3 gProj (MTOK / 128, DIMN / 64, 1);             // 16 x 16
    dim3 gFfn  (MTOK / 128, HIDDEN / 64, 1);           // 16 x 64
    dim3 gScore(SEQ / 128, SEQ / 64, BATCH * HEADS);   // 8 x 16 x 32
    dim3 gAV   (SEQ / 128, 1, BATCH * HEADS);          // 8 x 1 x 32
    dim3 gHead (MTOK / 128, VOCAB / 64, 1);            // 16 x 500
    dim3 gTr   (SEQ / 32, HEAD_DIM / 32, BATCH * HEADS);

    for (int l = 0; l < LAYERS; l++) {
        const float* wq = Wq + (long)l * DIMN * DIMN;
        const float* wk = Wk + (long)l * DIMN * DIMN;
        const float* wv = Wv + (long)l * DIMN * DIMN;
        const float* wo = Wo + (long)l * DIMN * DIMN;
        const float* wg = Wg + (long)l * HIDDEN * DIMN;
        const float* wu = Wu + (long)l * HIDDEN * DIMN;
        const float* wd = Wd + (long)l * DIMN * HIDDEN;

        rmsnorm_kernel<<<MTOK, 256>>>(h, ln1 + (long)l * DIMN, x);

        mma_gemm<false><<<gProj, 256, DYN>>>(x, DIMN, 0, 0, wq, DIMN, 0, 0,
                                             q, DIMN, 0, 0, DIMN, 1.0f, 1);
        mma_gemm<false><<<gProj, 256, DYN>>>(x, DIMN, 0, 0, wk, DIMN, 0, 0,
                                             k, DIMN, 0, 0, DIMN, 1.0f, 1);
        mma_gemm<false><<<gProj, 256, DYN>>>(x, DIMN, 0, 0, wv, DIMN, 0, 0,
                                             v, DIMN, 0, 0, DIMN, 1.0f, 1);

        // att = scale * q k^T  (batched over b,h; K = HEAD_DIM)
        mma_gemm<false><<<gScore, 256, DYN>>>(
            q, DIMN, (long)SEQ * DIMN, HEAD_DIM,
            k, DIMN, (long)SEQ * DIMN, HEAD_DIM,
            att, SEQ, (long)HEADS * SEQ * SEQ, (long)SEQ * SEQ,
            HEAD_DIM, scale, HEADS);

        softmax_kernel<<<BATCH * HEADS * SEQ, 256>>>(att);

        transpose_v_kernel<<<gTr, dim3(32, 8)>>>(v, vt);

        // y = att @ v  (NT with vt[b,h][d][s]; N = HEAD_DIM, K = SEQ)
        mma_gemm<false><<<gAV, 256, DYN>>>(
            att, SEQ, (long)HEADS * SEQ * SEQ, (long)SEQ * SEQ,
            vt, SEQ, (long)HEADS * HEAD_DIM * SEQ, (long)HEAD_DIM * SEQ,
            y, DIMN, (long)SEQ * DIMN, HEAD_DIM,
            SEQ, 1.0f, HEADS);

        // h += y @ Wo^T
        mma_gemm<true><<<gProj, 256, DYN>>>(y, DIMN, 0, 0, wo, DIMN, 0, 0,
                                            h, DIMN, 0, 0, DIMN, 1.0f, 1);

        rmsnorm_kernel<<<MTOK, 256>>>(h, ln2 + (long)l * DIMN, x);

        mma_gemm<false><<<gFfn, 256, DYN>>>(x, DIMN, 0, 0, wg, DIMN, 0, 0,
                                            gate, HIDDEN, 0, 0, DIMN, 1.0f, 1);
        mma_gemm<false><<<gFfn, 256, DYN>>>(x, DIMN, 0, 0, wu, DIMN, 0, 0,
                                            up, HIDDEN, 0, 0, DIMN, 1.0f, 1);

        silu_mul_kernel<<<(MTOK * (long)HIDDEN / 4) / 256, 256>>>((float4*)gate, (const float4*)up);

        // h += gate @ Wd^T
        mma_gemm<true><<<gProj, 256, DYN>>>(gate, HIDDEN, 0, 0, wd, HIDDEN, 0, 0,
                                            h, DIMN, 0, 0, HIDDEN, 1.0f, 1);
    }

    rmsnorm_kernel<<<MTOK, 256>>>(h, norm_w, x);
    mma_gemm<false><<<gHead, 256, DYN>>>(x, DIMN, 0, 0, lm_head, DIMN, 0, 0,
                                         out, VOCAB, 0, 0, DIMN, 1.0f, 1);
}

// round 8
// speedup vs baseline: 1.5831x; 1.0766x over previous
#include <cuda_runtime.h>
#include <math.h>
#include <stdint.h>

// ---------------- problem constants ----------------
#define DIMN     1024
#define HEADS    16
#define HEAD_DIM 64
#define LAYERS   4
#define HIDDEN   4096
#define VOCAB    32000
#define BATCH    2
#define SEQ      1024
#define MTOK     (BATCH*SEQ)
#define EPS      1e-6f

// ---------------- scratch ----------------
__device__ float g_h   [MTOK*DIMN];
__device__ float g_x   [MTOK*DIMN];
__device__ float g_q   [MTOK*DIMN];
__device__ float g_k   [MTOK*DIMN];
__device__ float g_v   [MTOK*DIMN];
__device__ float g_vt  [MTOK*DIMN];
__device__ float g_y   [MTOK*DIMN];
__device__ float g_att [(size_t)BATCH*HEADS*SEQ*SEQ];
__device__ float g_gate[MTOK*HIDDEN];
__device__ float g_up  [MTOK*HIDDEN];

// ---------------- PTX helpers ----------------
__device__ __forceinline__ uint32_t smem_u32(const void* p) {
    uint32_t a;
    asm("{ .reg .u64 t; cvta.to.shared.u64 t, %1; cvt.u32.u64 %0, t; }"
        : "=r"(a) : "l"(p));
    return a;
}

__device__ __forceinline__ void ldm4(uint32_t* r, uint32_t addr) {
    asm volatile("ldmatrix.sync.aligned.m8n8.x4.shared.b16 {%0,%1,%2,%3}, [%4];"
                 : "=r"(r[0]), "=r"(r[1]), "=r"(r[2]), "=r"(r[3]) : "r"(addr));
}

__device__ __forceinline__ void mma16816(float* c, const uint32_t* a, const uint32_t* b) {
    asm volatile("mma.sync.aligned.m16n8k16.row.col.f32.bf16.bf16.f32 "
                 "{%0,%1,%2,%3}, {%4,%5,%6,%7}, {%8,%9}, {%0,%1,%2,%3};"
                 : "+f"(c[0]), "+f"(c[1]), "+f"(c[2]), "+f"(c[3])
                 : "r"(a[0]), "r"(a[1]), "r"(a[2]), "r"(a[3]),
                   "r"(b[0]), "r"(b[1]));
}

// fp32 float4 -> hi/lo bf16 quads, stored to swizzled smem.
__device__ __forceinline__ void split_store(uint32_t hi_base, uint32_t lo_base,
                                            int row, int k4, float4 f) {
    uint32_t ux = __float_as_uint(f.x), uy = __float_as_uint(f.y);
    uint32_t uz = __float_as_uint(f.z), uw = __float_as_uint(f.w);
    uint32_t h01 = __byte_perm(ux, uy, 0x7632);
    uint32_t h23 = __byte_perm(uz, uw, 0x7632);
    float lx = f.x - __uint_as_float(ux & 0xFFFF0000u);
    float ly = f.y - __uint_as_float(uy & 0xFFFF0000u);
    float lz = f.z - __uint_as_float(uz & 0xFFFF0000u);
    float lw = f.w - __uint_as_float(uw & 0xFFFF0000u);
    uint32_t l01 = __byte_perm(__float_as_uint(lx), __float_as_uint(ly), 0x7632);
    uint32_t l23 = __byte_perm(__float_as_uint(lz), __float_as_uint(lw), 0x7632);
    int chunk = k4 >> 1, half = k4 & 1;
    uint32_t off = (uint32_t)(row * 64 + ((chunk ^ ((row >> 1) & 3)) << 4) + half * 8);
    asm volatile("st.shared.v2.b32 [%0], {%1,%2};" :: "r"(hi_base + off), "r"(h01), "r"(h23));
    asm volatile("st.shared.v2.b32 [%0], {%1,%2};" :: "r"(lo_base + off), "r"(l01), "r"(l23));
}

// ---------------- GEMM body (shared by both entry points) -----------------
// C = alpha * A * B^T [+C]; 128 x BN tile, BK=32, 256 thr (8 warps 2m x 4n).
template<int BN, bool ACCUM>
__device__ __forceinline__ void gemm_body(
    const float* __restrict__ A, int lda,
    const float* __restrict__ B, int ldb,
    float*       __restrict__ C, int ldc,
    int K, float alpha, int m0, int n0)
{
    constexpr int WN    = BN / 4;
    constexpr int NA    = WN / 8;
    constexpr int NB4   = BN / 32;
    constexpr int A_LO  = 8192;
    constexpr int B_HI  = 16384;
    constexpr int BLO_D = BN * 64;
    constexpr int STAGE = 16384 + BN * 128;

    extern __shared__ char smem[];
    const uint32_t sb0 = smem_u32(smem);

    const int tid = threadIdx.x, lane = tid & 31, wid = tid >> 5;
    const int wm = wid & 1, wn = wid >> 1;

    uint32_t offA[4][2], offB[NA / 2][2];
    #pragma unroll
    for (int am = 0; am < 4; am++)
        #pragma unroll
        for (int kh = 0; kh < 2; kh++) {
            int mrow  = wm * 64 + am * 16 + (lane & 7) + ((lane >> 3) & 1) * 8;
            int chunk = kh * 2 + ((lane >> 4) & 1);
            offA[am][kh] = (uint32_t)(mrow * 64 + ((chunk ^ ((mrow >> 1) & 3)) << 4));
        }
    #pragma unroll
    for (int p = 0; p < NA / 2; p++)
        #pragma unroll
        for (int kh = 0; kh < 2; kh++) {
            int nrow  = wn * WN + p * 16 + (lane & 7) + ((lane >> 4) & 1) * 8;
            int chunk = kh * 2 + ((lane >> 3) & 1);
            offB[p][kh] = (uint32_t)(B_HI + nrow * 64 + ((chunk ^ ((nrow >> 1) & 3)) << 4));
        }

    float acc[4][NA][4];
    #pragma unroll
    for (int i = 0; i < 4; i++)
        #pragma unroll
        for (int j = 0; j < NA; j++)
            #pragma unroll
            for (int e = 0; e < 4; e++) acc[i][j][e] = 0.0f;

    float4 pa[4], pb[NB4];
    auto LOADG = [&](int k0) {
        #pragma unroll
        for (int i = 0; i < 4; i++) {
            int idx = i * 256 + tid, row = idx >> 3, k4 = idx & 7;
            pa[i] = *(const float4*)&A[(long)(m0 + row) * lda + k0 + k4 * 4];
        }
        #pragma unroll
        for (int i = 0; i < NB4; i++) {
            int idx = i * 256 + tid, row = idx >> 3, k4 = idx & 7;
            pb[i] = *(const float4*)&B[(long)(n0 + row) * ldb + k0 + k4 * 4];
        }
    };
    auto STORES = [&](uint32_t base) {
        #pragma unroll
        for (int i = 0; i < 4; i++) {
            int idx = i * 256 + tid, row = idx >> 3, k4 = idx & 7;
            split_store(base, base + A_LO, row, k4, pa[i]);
        }
        #pragma unroll
        for (int i = 0; i < NB4; i++) {
            int idx = i * 256 + tid, row = idx >> 3, k4 = idx & 7;
            split_store(base + B_HI, base + B_HI + BLO_D, row, k4, pb[i]);
        }
    };

    const int nk = K >> 5;
    LOADG(0);
    STORES(sb0);
    __syncthreads();

    for (int t = 0; t < nk; t++) {
        const uint32_t sb = sb0 + (uint32_t)(t & 1) * STAGE;
        if (t + 1 < nk) LOADG((t + 1) * 32);

        #pragma unroll
        for (int kh = 0; kh < 2; kh++) {
            uint32_t ah[4][4], al[4][4];
            #pragma unroll
            for (int am = 0; am < 4; am++) {
                ldm4(ah[am], sb + offA[am][kh]);
                ldm4(al[am], sb + offA[am][kh] + A_LO);
            }
            uint32_t bh[NA / 2][4], bl[NA / 2][4];
            #pragma unroll
            for (int p = 0; p < NA / 2; p++) {
                ldm4(bh[p], sb + offB[p][kh]);
                ldm4(bl[p], sb + offB[p][kh] + BLO_D);
            }
            #pragma unroll
            for (int am = 0; am < 4; am++)
                #pragma unroll
                for (int na = 0; na < NA; na++) {
                    const uint32_t* bhp = &bh[na >> 1][(na & 1) * 2];
                    const uint32_t* blp = &bl[na >> 1][(na & 1) * 2];
                    mma16816(acc[am][na], ah[am], bhp);
                    mma16816(acc[am][na], ah[am], blp);
                    mma16816(acc[am][na], al[am], bhp);
                }
        }

        if (t + 1 < nk) STORES(sb0 + (uint32_t)((t & 1) ^ 1) * STAGE);
        __syncthreads();
    }

    #pragma unroll
    for (int am = 0; am < 4; am++)
        #pragma unroll
        for (int na = 0; na < NA; na++) {
            int row = m0 + wm * 64 + am * 16 + (lane >> 2);
            int col = n0 + wn * WN + na * 8 + (lane & 3) * 2;
            float* base0 = &C[(long)row * ldc + col];
            float* base1 = &C[(long)(row + 8) * ldc + col];
            float2 r0 = { alpha * acc[am][na][0], alpha * acc[am][na][1] };
            float2 r1 = { alpha * acc[am][na][2], alpha * acc[am][na][3] };
            if (ACCUM) {
                float2 o0 = *(float2*)base0, o1 = *(float2*)base1;
                r0.x += o0.x; r0.y += o0.y; r1.x += o1.x; r1.y += o1.y;
            }
            *(float2*)base0 = r0;
            *(float2*)base1 = r1;
        }
}

// ---- entry 1: batched (attention) / single GEMM, R4 semantics ----
template<int BN, bool ACCUM>
__global__ void __launch_bounds__(256, 1)
mma_gemm(const float* __restrict__ A, int lda, long sAb, long sAh,
         const float* __restrict__ B, int ldb, long sBb, long sBh,
         float*       __restrict__ C, int ldc, long sCb, long sCh,
         int K, float alpha, int hdiv)
{
    const int z = blockIdx.z;
    A += (z / hdiv) * sAb + (z % hdiv) * sAh;
    B += (z / hdiv) * sBb + (z % hdiv) * sBh;
    C += (z / hdiv) * sCb + (z % hdiv) * sCh;
    gemm_body<BN, ACCUM>(A, lda, B, ldb, C, ldc, K, alpha,
                         blockIdx.x * 128, blockIdx.y * BN);
}

// ---- entry 2: multi-matrix (shared A, z selects B/C) — fused QKV / gate+up
struct P3 {
    const float *B0, *B1, *B2;
    float *C0, *C1, *C2;
};

template<int BN>
__global__ void __launch_bounds__(256, 1)
mma_gemm_multi(const float* __restrict__ A, int lda, P3 p,
               int ldb, int ldc, int K, float alpha)
{
    const int z = blockIdx.z;
    const float* B = (z == 0) ? p.B0 : (z == 1) ? p.B1 : p.B2;
    float*       C = (z == 0) ? p.C0 : (z == 1) ? p.C1 : p.C2;
    gemm_body<BN, false>(A, lda, B, ldb, C, ldc, K, alpha,
                         blockIdx.x * 128, blockIdx.y * BN);
}

// ---------------- elementwise kernels ----------------
__global__ void embed_kernel(const int* __restrict__ tokens,
                             const float* __restrict__ embed,
                             float* __restrict__ h)
{
    int row = blockIdx.x;
    int tok = tokens[row];
    ((float4*)(h + (long)row * DIMN))[threadIdx.x] =
        ((const float4*)(embed + (long)tok * DIMN))[threadIdx.x];
}

__global__ void rmsnorm_kernel(const float* __restrict__ x,
                               const float* __restrict__ w,
                               float* __restrict__ out)
{
    int row = blockIdx.x;
    float4 v = ((const float4*)(x + (long)row * DIMN))[threadIdx.x];
    float ss = v.x*v.x + v.y*v.y + v.z*v.z + v.w*v.w;
    __shared__ float red[8];
    #pragma unroll
    for (int o = 16; o > 0; o >>= 1) ss += __shfl_xor_sync(0xFFFFFFFFu, ss, o);
    if ((threadIdx.x & 31) == 0) red[threadIdx.x >> 5] = ss;
    __syncthreads();
    if (threadIdx.x < 8) {
        float s = red[threadIdx.x];
        #pragma unroll
        for (int o = 4; o > 0; o >>= 1) s += __shfl_xor_sync(0xFFu, s, o);
        if (threadIdx.x == 0) red[0] = s;
    }
    __syncthreads();
    float scale = rsqrtf(red[0] * (1.0f / DIMN) + EPS);
    float4 wv = ((const float4*)w)[threadIdx.x];
    float4 o4 = { v.x*scale*wv.x, v.y*scale*wv.y, v.z*scale*wv.z, v.w*scale*wv.w };
    ((float4*)(out + (long)row * DIMN))[threadIdx.x] = o4;
}

__global__ void softmax_kernel(float* __restrict__ att)
{
    long row = blockIdx.x;
    float4* p = (float4*)(att + row * (long)SEQ);
    float4 v = p[threadIdx.x];
    __shared__ float red[8];
    float mx = fmaxf(fmaxf(v.x, v.y), fmaxf(v.z, v.w));
    #pragma unroll
    for (int o = 16; o > 0; o >>= 1) mx = fmaxf(mx, __shfl_xor_sync(0xFFFFFFFFu, mx, o));
    if ((threadIdx.x & 31) == 0) red[threadIdx.x >> 5] = mx;
    __syncthreads();
    if (threadIdx.x < 8) {
        float s = red[threadIdx.x];
        #pragma unroll
        for (int o = 4; o > 0; o >>= 1) s = fmaxf(s, __shfl_xor_sync(0xFFu, s, o));
        if (threadIdx.x == 0) red[0] = s;
    }
    __syncthreads();
    mx = red[0];
    __syncthreads();
    v.x = __expf(v.x - mx); v.y = __expf(v.y - mx);
    v.z = __expf(v.z - mx); v.w = __expf(v.w - mx);
    float sum = v.x + v.y + v.z + v.w;
    #pragma unroll
    for (int o = 16; o > 0; o >>= 1) sum += __shfl_xor_sync(0xFFFFFFFFu, sum, o);
    if ((threadIdx.x & 31) == 0) red[threadIdx.x >> 5] = sum;
    __syncthreads();
    if (threadIdx.x < 8) {
        float s = red[threadIdx.x];
        #pragma unroll
        for (int o = 4; o > 0; o >>= 1) s += __shfl_xor_sync(0xFFu, s, o);
        if (threadIdx.x == 0) red[0] = s;
    }
    __syncthreads();
    float inv = 1.0f / red[0];
    v.x *= inv; v.y *= inv; v.z *= inv; v.w *= inv;
    p[threadIdx.x] = v;
}

__global__ void silu_mul_kernel(float4* __restrict__ g, const float4* __restrict__ u)
{
    long i = (long)blockIdx.x * blockDim.x + threadIdx.x;
    float4 gv = g[i], uv = u[i];
    gv.x = gv.x / (1.0f + __expf(-gv.x)) * uv.x;
    gv.y = gv.y / (1.0f + __expf(-gv.y)) * uv.y;
    gv.z = gv.z / (1.0f + __expf(-gv.z)) * uv.z;
    gv.w = gv.w / (1.0f + __expf(-gv.w)) * uv.w;
    g[i] = gv;
}

// vt[(b*H+h)][d][s] = v[b*SEQ+s][h*64+d]
__global__ void transpose_v_kernel(const float* __restrict__ v, float* __restrict__ vt)
{
    __shared__ float t[32][33];
    int bh = blockIdx.z, b = bh >> 4, hh = bh & 15;
    int s0 = blockIdx.x * 32, d0 = blockIdx.y * 32;
    int tx = threadIdx.x, ty = threadIdx.y;    // 32 x 8
    #pragma unroll
    for (int j = 0; j < 32; j += 8)
        t[ty + j][tx] = v[(long)(b * SEQ + s0 + ty + j) * DIMN + hh * HEAD_DIM + d0 + tx];
    __syncthreads();
    #pragma unroll
    for (int j = 0; j < 32; j += 8)
        vt[((long)bh * HEAD_DIM + d0 + ty + j) * SEQ + s0 + tx] = t[tx][ty + j];
}

// ---------------- launcher ----------------
extern "C" void kernel_launch(void* const* d_in, const int* in_sizes, int n_in,
                              void* d_out, int out_size)
{
    const int*   tokens  = (const int*)  d_in[0];
    const float* embed   = (const float*)d_in[1];
    const float* Wq      = (const float*)d_in[2];
    const float* Wk      = (const float*)d_in[3];
    const float* Wv      = (const float*)d_in[4];
    const float* Wo      = (const float*)d_in[5];
    const float* Wg      = (const float*)d_in[6];
    const float* Wu      = (const float*)d_in[7];
    const float* Wd      = (const float*)d_in[8];
    const float* ln1     = (const float*)d_in[9];
    const float* ln2     = (const float*)d_in[10];
    const float* norm_w  = (const float*)d_in[11];
    const float* lm_head = (const float*)d_in[12];
    float* out = (float*)d_out;

    float *h, *x, *q, *k, *v, *vt, *y, *att, *gate, *up;
    cudaGetSymbolAddress((void**)&h,    g_h);
    cudaGetSymbolAddress((void**)&x,    g_x);
    cudaGetSymbolAddress((void**)&q,    g_q);
    cudaGetSymbolAddress((void**)&k,    g_k);
    cudaGetSymbolAddress((void**)&v,    g_v);
    cudaGetSymbolAddress((void**)&vt,   g_vt);
    cudaGetSymbolAddress((void**)&y,    g_y);
    cudaGetSymbolAddress((void**)&att,  g_att);
    cudaGetSymbolAddress((void**)&gate, g_gate);
    cudaGetSymbolAddress((void**)&up,   g_up);

    const int DYN128 = 2 * (16384 + 128 * 128);   // 65536
    const int DYN64  = 2 * (16384 + 64 * 128);    // 49152
    cudaFuncSetAttribute(mma_gemm<128, false>, cudaFuncAttributeMaxDynamicSharedMemorySize, DYN128);
    cudaFuncSetAttribute(mma_gemm<128, true>,  cudaFuncAttributeMaxDynamicSharedMemorySize, DYN128);
    cudaFuncSetAttribute(mma_gemm<64,  false>, cudaFuncAttributeMaxDynamicSharedMemorySize, DYN64);
    cudaFuncSetAttribute(mma_gemm_multi<128>,  cudaFuncAttributeMaxDynamicSharedMemorySize, DYN128);

    const float scale = 1.0f / sqrtf((float)HEAD_DIM);

    embed_kernel<<<MTOK, 256>>>(tokens, embed, h);

    dim3 gQKV  (MTOK / 128, DIMN / 128, 3);            // 16 x 8 x 3 = 384 CTAs
    dim3 gGU   (MTOK / 128, HIDDEN / 128, 2);          // 16 x 32 x 2 = 1024 CTAs
    dim3 gProj (MTOK / 128, DIMN / 128, 1);            // 16 x 8
    dim3 gScore(SEQ / 128, SEQ / 128, BATCH * HEADS);  // 8 x 8 x 32
    dim3 gAV   (SEQ / 128, 1, BATCH * HEADS);          // 8 x 1 x 32
    dim3 gHead (MTOK / 128, VOCAB / 128, 1);           // 16 x 250
    dim3 gTr   (SEQ / 32, HEAD_DIM / 32, BATCH * HEADS);

    for (int l = 0; l < LAYERS; l++) {
        const float* wq = Wq + (long)l * DIMN * DIMN;
        const float* wk = Wk + (long)l * DIMN * DIMN;
        const float* wv = Wv + (long)l * DIMN * DIMN;
        const float* wo = Wo + (long)l * DIMN * DIMN;
        const float* wg = Wg + (long)l * HIDDEN * DIMN;
        const float* wu = Wu + (long)l * HIDDEN * DIMN;
        const float* wd = Wd + (long)l * DIMN * HIDDEN;

        rmsnorm_kernel<<<MTOK, 256>>>(h, ln1 + (long)l * DIMN, x);

        // fused q,k,v = x @ {Wq,Wk,Wv}^T  (one launch, 384 CTAs)
        {
            P3 p = { wq, wk, wv, q, k, v };
            mma_gemm_multi<128><<<gQKV, 256, DYN128>>>(x, DIMN, p, DIMN, DIMN, DIMN, 1.0f);
        }

        // att = scale * q k^T  (batched over b,h; K = HEAD_DIM)
        mma_gemm<128, false><<<gScore, 256, DYN128>>>(
            q, DIMN, (long)SEQ * DIMN, HEAD_DIM,
            k, DIMN, (long)SEQ * DIMN, HEAD_DIM,
            att, SEQ, (long)HEADS * SEQ * SEQ, (long)SEQ * SEQ,
            HEAD_DIM, scale, HEADS);

        softmax_kernel<<<BATCH * HEADS * SEQ, 256>>>(att);

        transpose_v_kernel<<<gTr, dim3(32, 8)>>>(v, vt);

        // y = att @ v  (NT with vt[b,h][d][s]; N = HEAD_DIM, K = SEQ)
        mma_gemm<64, false><<<gAV, 256, DYN64>>>(
            att, SEQ, (long)HEADS * SEQ * SEQ, (long)SEQ * SEQ,
            vt, SEQ, (long)HEADS * HEAD_DIM * SEQ, (long)HEAD_DIM * SEQ,
            y, DIMN, (long)SEQ * DIMN, HEAD_DIM,
            SEQ, 1.0f, HEADS);

        // h += y @ Wo^T
        mma_gemm<128, true><<<gProj, 256, DYN128>>>(y, DIMN, 0, 0, wo, DIMN, 0, 0,
                                                    h, DIMN, 0, 0, DIMN, 1.0f, 1);

        rmsnorm_kernel<<<MTOK, 256>>>(h, ln2 + (long)l * DIMN, x);

        // fused gate,up = x @ {Wg,Wu}^T  (one launch, 1024 CTAs)
        {
            P3 p = { wg, wu, wu, gate, up, up };
            dim3 g2 = gGU;
            mma_gemm_multi<128><<<g2, 256, DYN128>>>(x, DIMN, p, DIMN, HIDDEN, DIMN, 1.0f);
        }

        silu_mul_kernel<<<(MTOK * (long)HIDDEN / 4) / 256, 256>>>((float4*)gate, (const float4*)up);

        // h += gate @ Wd^T
        mma_gemm<128, true><<<gProj, 256, DYN128>>>(gate, HIDDEN, 0, 0, wd, HIDDEN, 0, 0,
                                                    h, DIMN, 0, 0, HIDDEN, 1.0f, 1);
    }

    rmsnorm_kernel<<<MTOK, 256>>>(h, norm_w, x);
    mma_gemm<128, false><<<gHead, 256, DYN128>>>(x, DIMN, 0, 0, lm_head, DIMN, 0, 0,
                                                 out, VOCAB, 0, 0, DIMN, 1.0f, 1);
}

// round 9
// speedup vs baseline: 1.7583x; 1.1107x over previous
#include <cuda_runtime.h>
#include <math.h>
#include <stdint.h>

// ---------------- problem constants ----------------
#define DIMN     1024
#define HEADS    16
#define HEAD_DIM 64
#define LAYERS   4
#define HIDDEN   4096
#define VOCAB    32000
#define BATCH    2
#define SEQ      1024
#define MTOK     (BATCH*SEQ)
#define EPS      1e-6f

// ---------------- scratch ----------------
__device__ float g_h   [MTOK*DIMN];
__device__ float g_x   [MTOK*DIMN];
__device__ float g_q   [MTOK*DIMN];
__device__ float g_k   [MTOK*DIMN];
__device__ float g_v   [MTOK*DIMN];
__device__ float g_vt  [MTOK*DIMN];
__device__ float g_y   [MTOK*DIMN];
__device__ float g_gate[MTOK*HIDDEN];
__device__ float g_up  [MTOK*HIDDEN];

// ---------------- PTX helpers ----------------
__device__ __forceinline__ uint32_t smem_u32(const void* p) {
    uint32_t a;
    asm("{ .reg .u64 t; cvta.to.shared.u64 t, %1; cvt.u32.u64 %0, t; }"
        : "=r"(a) : "l"(p));
    return a;
}

__device__ __forceinline__ void ldm4(uint32_t* r, uint32_t addr) {
    asm volatile("ldmatrix.sync.aligned.m8n8.x4.shared.b16 {%0,%1,%2,%3}, [%4];"
                 : "=r"(r[0]), "=r"(r[1]), "=r"(r[2]), "=r"(r[3]) : "r"(addr));
}

__device__ __forceinline__ void mma16816(float* c, const uint32_t* a, const uint32_t* b) {
    asm volatile("mma.sync.aligned.m16n8k16.row.col.f32.bf16.bf16.f32 "
                 "{%0,%1,%2,%3}, {%4,%5,%6,%7}, {%8,%9}, {%0,%1,%2,%3};"
                 : "+f"(c[0]), "+f"(c[1]), "+f"(c[2]), "+f"(c[3])
                 : "r"(a[0]), "r"(a[1]), "r"(a[2]), "r"(a[3]),
                   "r"(b[0]), "r"(b[1]));
}

__device__ __forceinline__ uint32_t pk_hi(float a, float b) {
    return __byte_perm(__float_as_uint(a), __float_as_uint(b), 0x7632);
}
__device__ __forceinline__ uint32_t pk_lo(float a, float b) {
    float la = a - __uint_as_float(__float_as_uint(a) & 0xFFFF0000u);
    float lb = b - __uint_as_float(__float_as_uint(b) & 0xFFFF0000u);
    return __byte_perm(__float_as_uint(la), __float_as_uint(lb), 0x7632);
}

// fp32 float4 -> hi/lo bf16 quads, stored to swizzled smem.
__device__ __forceinline__ void split_store(uint32_t hi_base, uint32_t lo_base,
                                            int row, int k4, float4 f) {
    uint32_t h01 = pk_hi(f.x, f.y), h23 = pk_hi(f.z, f.w);
    uint32_t l01 = pk_lo(f.x, f.y), l23 = pk_lo(f.z, f.w);
    int chunk = k4 >> 1, half = k4 & 1;
    uint32_t off = (uint32_t)(row * 64 + ((chunk ^ ((row >> 1) & 3)) << 4) + half * 8);
    asm volatile("st.shared.v2.b32 [%0], {%1,%2};" :: "r"(hi_base + off), "r"(h01), "r"(h23));
    asm volatile("st.shared.v2.b32 [%0], {%1,%2};" :: "r"(lo_base + off), "r"(l01), "r"(l23));
}

// ---------------- GEMM body (validated since R4) -----------------
template<int BN, bool ACCUM>
__device__ __forceinline__ void gemm_body(
    const float* __restrict__ A, int lda,
    const float* __restrict__ B, int ldb,
    float*       __restrict__ C, int ldc,
    int K, float alpha, int m0, int n0)
{
    constexpr int WN    = BN / 4;
    constexpr int NA    = WN / 8;
    constexpr int NB4   = BN / 32;
    constexpr int A_LO  = 8192;
    constexpr int B_HI  = 16384;
    constexpr int BLO_D = BN * 64;
    constexpr int STAGE = 16384 + BN * 128;

    extern __shared__ char smem[];
    const uint32_t sb0 = smem_u32(smem);

    const int tid = threadIdx.x, lane = tid & 31, wid = tid >> 5;
    const int wm = wid & 1, wn = wid >> 1;

    uint32_t offA[4][2], offB[NA / 2][2];
    #pragma unroll
    for (int am = 0; am < 4; am++)
        #pragma unroll
        for (int kh = 0; kh < 2; kh++) {
            int mrow  = wm * 64 + am * 16 + (lane & 7) + ((lane >> 3) & 1) * 8;
            int chunk = kh * 2 + ((lane >> 4) & 1);
            offA[am][kh] = (uint32_t)(mrow * 64 + ((chunk ^ ((mrow >> 1) & 3)) << 4));
        }
    #pragma unroll
    for (int p = 0; p < NA / 2; p++)
        #pragma unroll
        for (int kh = 0; kh < 2; kh++) {
            int nrow  = wn * WN + p * 16 + (lane & 7) + ((lane >> 4) & 1) * 8;
            int chunk = kh * 2 + ((lane >> 3) & 1);
            offB[p][kh] = (uint32_t)(B_HI + nrow * 64 + ((chunk ^ ((nrow >> 1) & 3)) << 4));
        }

    float acc[4][NA][4];
    #pragma unroll
    for (int i = 0; i < 4; i++)
        #pragma unroll
        for (int j = 0; j < NA; j++)
            #pragma unroll
            for (int e = 0; e < 4; e++) acc[i][j][e] = 0.0f;

    float4 pa[4], pb[NB4];
    auto LOADG = [&](int k0) {
        #pragma unroll
        for (int i = 0; i < 4; i++) {
            int idx = i * 256 + tid, row = idx >> 3, k4 = idx & 7;
            pa[i] = *(const float4*)&A[(long)(m0 + row) * lda + k0 + k4 * 4];
        }
        #pragma unroll
        for (int i = 0; i < NB4; i++) {
            int idx = i * 256 + tid, row = idx >> 3, k4 = idx & 7;
            pb[i] = *(const float4*)&B[(long)(n0 + row) * ldb + k0 + k4 * 4];
        }
    };
    auto STORES = [&](uint32_t base) {
        #pragma unroll
        for (int i = 0; i < 4; i++) {
            int idx = i * 256 + tid, row = idx >> 3, k4 = idx & 7;
            split_store(base, base + A_LO, row, k4, pa[i]);
        }
        #pragma unroll
        for (int i = 0; i < NB4; i++) {
            int idx = i * 256 + tid, row = idx >> 3, k4 = idx & 7;
            split_store(base + B_HI, base + B_HI + BLO_D, row, k4, pb[i]);
        }
    };

    const int nk = K >> 5;
    LOADG(0);
    STORES(sb0);
    __syncthreads();

    for (int t = 0; t < nk; t++) {
        const uint32_t sb = sb0 + (uint32_t)(t & 1) * STAGE;
        if (t + 1 < nk) LOADG((t + 1) * 32);

        #pragma unroll
        for (int kh = 0; kh < 2; kh++) {
            uint32_t ah[4][4], al[4][4];
            #pragma unroll
            for (int am = 0; am < 4; am++) {
                ldm4(ah[am], sb + offA[am][kh]);
                ldm4(al[am], sb + offA[am][kh] + A_LO);
            }
            uint32_t bh[NA / 2][4], bl[NA / 2][4];
            #pragma unroll
            for (int p = 0; p < NA / 2; p++) {
                ldm4(bh[p], sb + offB[p][kh]);
                ldm4(bl[p], sb + offB[p][kh] + BLO_D);
            }
            #pragma unroll
            for (int am = 0; am < 4; am++)
                #pragma unroll
                for (int na = 0; na < NA; na++) {
                    const uint32_t* bhp = &bh[na >> 1][(na & 1) * 2];
                    const uint32_t* blp = &bl[na >> 1][(na & 1) * 2];
                    mma16816(acc[am][na], ah[am], bhp);
                    mma16816(acc[am][na], ah[am], blp);
                    mma16816(acc[am][na], al[am], bhp);
                }
        }

        if (t + 1 < nk) STORES(sb0 + (uint32_t)((t & 1) ^ 1) * STAGE);
        __syncthreads();
    }

    #pragma unroll
    for (int am = 0; am < 4; am++)
        #pragma unroll
        for (int na = 0; na < NA; na++) {
            int row = m0 + wm * 64 + am * 16 + (lane >> 2);
            int col = n0 + wn * WN + na * 8 + (lane & 3) * 2;
            float* base0 = &C[(long)row * ldc + col];
            float* base1 = &C[(long)(row + 8) * ldc + col];
            float2 r0 = { alpha * acc[am][na][0], alpha * acc[am][na][1] };
            float2 r1 = { alpha * acc[am][na][2], alpha * acc[am][na][3] };
            if (ACCUM) {
                float2 o0 = *(float2*)base0, o1 = *(float2*)base1;
                r0.x += o0.x; r0.y += o0.y; r1.x += o1.x; r1.y += o1.y;
            }
            *(float2*)base0 = r0;
            *(float2*)base1 = r1;
        }
}

template<int BN, bool ACCUM>
__global__ void __launch_bounds__(256, 1)
mma_gemm(const float* __restrict__ A, int lda,
         const float* __restrict__ B, int ldb,
         float*       __restrict__ C, int ldc,
         int K, float alpha)
{
    gemm_body<BN, ACCUM>(A, lda, B, ldb, C, ldc, K, alpha,
                         blockIdx.x * 128, blockIdx.y * BN);
}

struct P3 {
    const float *B0, *B1, *B2;
    float *C0, *C1, *C2;
};

template<int BN>
__global__ void __launch_bounds__(256, 1)
mma_gemm_multi(const float* __restrict__ A, int lda, P3 p,
               int ldb, int ldc, int K, float alpha)
{
    const int z = blockIdx.z;
    const float* B = (z == 0) ? p.B0 : (z == 1) ? p.B1 : p.B2;
    float*       C = (z == 0) ? p.C0 : (z == 1) ? p.C1 : p.C2;
    gemm_body<BN, false>(A, lda, B, ldb, C, ldc, K, alpha,
                         blockIdx.x * 128, blockIdx.y * BN);
}

// ================= flash attention ================================
// grid (SEQ/128, 1, BATCH*HEADS); 256 threads (8 warps, 2m x 4n).
// y[token][h*64+d] = softmax(q k^T / 8) @ v, no mask.
#define FA_QH 0
#define FA_QL 16384
#define FA_KH 32768
#define FA_KL 49152
#define FA_VH 65536
#define FA_VL 81920
#define FA_PH 98304
#define FA_PL 131072
#define FA_SMX 163840
#define FA_SSM 165888
#define FA_BYTES 167936

__global__ void __launch_bounds__(256, 1)
flash_attn(const float* __restrict__ q, const float* __restrict__ k,
           const float* __restrict__ vt, float* __restrict__ y)
{
    extern __shared__ char smem[];
    const uint32_t sb = smem_u32(smem);
    float* smx = (float*)(smem + FA_SMX);
    float* ssm = (float*)(smem + FA_SSM);

    const int tid = threadIdx.x, lane = tid & 31, wid = tid >> 5;
    const int wm = wid & 1, wn = wid >> 1;
    const int bh = blockIdx.z, b = bh >> 4, hh = bh & 15;
    const int q0 = blockIdx.x * 128;

    // A-style ldmatrix offsets (Q and P share the mapping)
    uint32_t offA[4][2];
    #pragma unroll
    for (int am = 0; am < 4; am++)
        #pragma unroll
        for (int khi = 0; khi < 2; khi++) {
            int arow  = wm * 64 + am * 16 + (lane & 7) + ((lane >> 3) & 1) * 8;
            int chunk = khi * 2 + ((lane >> 4) & 1);
            offA[am][khi] = (uint32_t)(arow * 64 + ((chunk ^ ((arow >> 1) & 3)) << 4));
        }
    // B-style offsets for K (n-tile 32/warp) and V (n-tile 16/warp)
    uint32_t offK[2][2], offV[2];
    #pragma unroll
    for (int p = 0; p < 2; p++)
        #pragma unroll
        for (int khi = 0; khi < 2; khi++) {
            int brow  = wn * 32 + p * 16 + (lane & 7) + ((lane >> 4) & 1) * 8;
            int chunk = khi * 2 + ((lane >> 3) & 1);
            offK[p][khi] = (uint32_t)(brow * 64 + ((chunk ^ ((brow >> 1) & 3)) << 4));
        }
    #pragma unroll
    for (int khi = 0; khi < 2; khi++) {
        int brow  = wn * 16 + (lane & 7) + ((lane >> 4) & 1) * 8;
        int chunk = khi * 2 + ((lane >> 3) & 1);
        offV[khi] = (uint32_t)(brow * 64 + ((chunk ^ ((brow >> 1) & 3)) << 4));
    }

    // load Q tile (scaled by 1/8, exact), split hi/lo
    #pragma unroll
    for (int i = 0; i < 8; i++) {
        int idx = i * 256 + tid, row = idx >> 4, k4 = idx & 15;
        float4 f = *(const float4*)&q[(long)(b * SEQ + q0 + row) * DIMN + hh * 64 + k4 * 4];
        f.x *= 0.125f; f.y *= 0.125f; f.z *= 0.125f; f.w *= 0.125f;
        split_store(sb + FA_QH + (k4 >> 3) * 8192, sb + FA_QL + (k4 >> 3) * 8192,
                    row, k4 & 7, f);
    }

    float o[4][2][4];
    float m_r[4][2], l_r[4][2];
    #pragma unroll
    for (int am = 0; am < 4; am++) {
        m_r[am][0] = m_r[am][1] = -1e30f;
        l_r[am][0] = l_r[am][1] = 0.0f;
        #pragma unroll
        for (int na = 0; na < 2; na++)
            #pragma unroll
            for (int e = 0; e < 4; e++) o[am][na][e] = 0.0f;
    }

    const int rb = wm * 64 + (lane >> 2);

    for (int s0 = 0; s0 < SEQ; s0 += 128) {
        __syncthreads();   // prev iter's MMAs done before overwriting K/V

        #pragma unroll
        for (int i = 0; i < 8; i++) {     // K tile 128x64
            int idx = i * 256 + tid, row = idx >> 4, k4 = idx & 15;
            float4 f = *(const float4*)&k[(long)(b * SEQ + s0 + row) * DIMN + hh * 64 + k4 * 4];
            split_store(sb + FA_KH + (k4 >> 3) * 8192, sb + FA_KL + (k4 >> 3) * 8192,
                        row, k4 & 7, f);
        }
        #pragma unroll
        for (int i = 0; i < 8; i++) {     // V tile 64 dims x 128 s (from vt)
            int idx = i * 256 + tid, row = idx >> 5, sc = idx & 31;
            float4 f = *(const float4*)&vt[((long)bh * 64 + row) * SEQ + s0 + sc * 4];
            split_store(sb + FA_VH + (sc >> 3) * 4096, sb + FA_VL + (sc >> 3) * 4096,
                        row, sc & 7, f);
        }
        __syncthreads();

        // S = Qs K^T  (128x128, K=64)
        float sf[4][4][4];
        #pragma unroll
        for (int am = 0; am < 4; am++)
            #pragma unroll
            for (int na = 0; na < 4; na++)
                #pragma unroll
                for (int e = 0; e < 4; e++) sf[am][na][e] = 0.0f;

        #pragma unroll
        for (int kb = 0; kb < 2; kb++)
            #pragma unroll
            for (int khi = 0; khi < 2; khi++) {
                uint32_t ah[4][4], al[4][4];
                #pragma unroll
                for (int am = 0; am < 4; am++) {
                    ldm4(ah[am], sb + FA_QH + kb * 8192 + offA[am][khi]);
                    ldm4(al[am], sb + FA_QL + kb * 8192 + offA[am][khi]);
                }
                uint32_t bhf[2][4], blf[2][4];
                #pragma unroll
                for (int p = 0; p < 2; p++) {
                    ldm4(bhf[p], sb + FA_KH + kb * 8192 + offK[p][khi]);
                    ldm4(blf[p], sb + FA_KL + kb * 8192 + offK[p][khi]);
                }
                #pragma unroll
                for (int am = 0; am < 4; am++)
                    #pragma unroll
                    for (int na = 0; na < 4; na++) {
                        const uint32_t* bhp = &bhf[na >> 1][(na & 1) * 2];
                        const uint32_t* blp = &blf[na >> 1][(na & 1) * 2];
                        mma16816(sf[am][na], ah[am], bhp);
                        mma16816(sf[am][na], ah[am], blp);
                        mma16816(sf[am][na], al[am], bhp);
                    }
            }

        // row max partials
        #pragma unroll
        for (int am = 0; am < 4; am++) {
            float v0 = -1e30f, v1 = -1e30f;
            #pragma unroll
            for (int na = 0; na < 4; na++) {
                v0 = fmaxf(v0, fmaxf(sf[am][na][0], sf[am][na][1]));
                v1 = fmaxf(v1, fmaxf(sf[am][na][2], sf[am][na][3]));
            }
            v0 = fmaxf(v0, __shfl_xor_sync(0xFFFFFFFFu, v0, 1));
            v0 = fmaxf(v0, __shfl_xor_sync(0xFFFFFFFFu, v0, 2));
            v1 = fmaxf(v1, __shfl_xor_sync(0xFFFFFFFFu, v1, 1));
            v1 = fmaxf(v1, __shfl_xor_sync(0xFFFFFFFFu, v1, 2));
            if ((lane & 3) == 0) {
                smx[(rb + am * 16) * 4 + wn] = v0;
                smx[(rb + am * 16 + 8) * 4 + wn] = v1;
            }
        }
        __syncthreads();

        float csc[4][2];
        #pragma unroll
        for (int am = 0; am < 4; am++) {
            int r0 = rb + am * 16, r1 = r0 + 8;
            float tm0 = fmaxf(fmaxf(smx[r0 * 4 + 0], smx[r0 * 4 + 1]),
                              fmaxf(smx[r0 * 4 + 2], smx[r0 * 4 + 3]));
            float tm1 = fmaxf(fmaxf(smx[r1 * 4 + 0], smx[r1 * 4 + 1]),
                              fmaxf(smx[r1 * 4 + 2], smx[r1 * 4 + 3]));
            float mn0 = fmaxf(m_r[am][0], tm0);
            float mn1 = fmaxf(m_r[am][1], tm1);
            csc[am][0] = __expf(m_r[am][0] - mn0);
            csc[am][1] = __expf(m_r[am][1] - mn1);
            m_r[am][0] = mn0; m_r[am][1] = mn1;

            float rs0 = 0.0f, rs1 = 0.0f;
            #pragma unroll
            for (int na = 0; na < 4; na++) {
                float p0 = __expf(sf[am][na][0] - mn0);
                float p1 = __expf(sf[am][na][1] - mn0);
                float p2 = __expf(sf[am][na][2] - mn1);
                float p3 = __expf(sf[am][na][3] - mn1);
                rs0 += p0 + p1; rs1 += p2 + p3;
                int c0col = wn * 32 + na * 8 + (lane & 3) * 2;
                int kb = c0col >> 5, cc = c0col & 31;
                uint32_t sw = (uint32_t)((((cc >> 3)) << 4)) ;
                uint32_t o0 = (uint32_t)(kb * 8192 + r0 * 64 +
                              (((cc >> 3) ^ ((r0 >> 1) & 3)) << 4) +
                              ((cc >> 2) & 1) * 8 + (cc & 3) * 2);
                uint32_t o1 = (uint32_t)(kb * 8192 + r1 * 64 +
                              (((cc >> 3) ^ ((r1 >> 1) & 3)) << 4) +
                              ((cc >> 2) & 1) * 8 + (cc & 3) * 2);
                (void)sw;
                *(uint32_t*)(smem + FA_PH + o0) = pk_hi(p0, p1);
                *(uint32_t*)(smem + FA_PL + o0) = pk_lo(p0, p1);
                *(uint32_t*)(smem + FA_PH + o1) = pk_hi(p2, p3);
                *(uint32_t*)(smem + FA_PL + o1) = pk_lo(p2, p3);
            }
            rs0 += __shfl_xor_sync(0xFFFFFFFFu, rs0, 1);
            rs0 += __shfl_xor_sync(0xFFFFFFFFu, rs0, 2);
            rs1 += __shfl_xor_sync(0xFFFFFFFFu, rs1, 1);
            rs1 += __shfl_xor_sync(0xFFFFFFFFu, rs1, 2);
            if ((lane & 3) == 0) {
                ssm[r0 * 4 + wn] = rs0;
                ssm[r1 * 4 + wn] = rs1;
            }
        }
        __syncthreads();

        #pragma unroll
        for (int am = 0; am < 4; am++) {
            int r0 = rb + am * 16, r1 = r0 + 8;
            float s0s = ssm[r0 * 4 + 0] + ssm[r0 * 4 + 1] + ssm[r0 * 4 + 2] + ssm[r0 * 4 + 3];
            float s1s = ssm[r1 * 4 + 0] + ssm[r1 * 4 + 1] + ssm[r1 * 4 + 2] + ssm[r1 * 4 + 3];
            l_r[am][0] = l_r[am][0] * csc[am][0] + s0s;
            l_r[am][1] = l_r[am][1] * csc[am][1] + s1s;
            #pragma unroll
            for (int na = 0; na < 2; na++) {
                o[am][na][0] *= csc[am][0]; o[am][na][1] *= csc[am][0];
                o[am][na][2] *= csc[am][1]; o[am][na][3] *= csc[am][1];
            }
        }

        // O += P V   (128x64, K=128)
        #pragma unroll
        for (int kb = 0; kb < 4; kb++)
            #pragma unroll
            for (int khi = 0; khi < 2; khi++) {
                uint32_t ah[4][4], al[4][4];
                #pragma unroll
                for (int am = 0; am < 4; am++) {
                    ldm4(ah[am], sb + FA_PH + kb * 8192 + offA[am][khi]);
                    ldm4(al[am], sb + FA_PL + kb * 8192 + offA[am][khi]);
                }
                uint32_t bhf[4], blf[4];
                ldm4(bhf, sb + FA_VH + kb * 4096 + offV[khi]);
                ldm4(blf, sb + FA_VL + kb * 4096 + offV[khi]);
                #pragma unroll
                for (int am = 0; am < 4; am++)
                    #pragma unroll
                    for (int na = 0; na < 2; na++) {
                        const uint32_t* bhp = &bhf[na * 2];
                        const uint32_t* blp = &blf[na * 2];
                        mma16816(o[am][na], ah[am], bhp);
                        mma16816(o[am][na], ah[am], blp);
                        mma16816(o[am][na], al[am], bhp);
                    }
            }
    }

    // epilogue: y = O / l
    #pragma unroll
    for (int am = 0; am < 4; am++) {
        float inv0 = 1.0f / l_r[am][0];
        float inv1 = 1.0f / l_r[am][1];
        long tok0 = (long)(b * SEQ + q0 + wm * 64 + am * 16 + (lane >> 2));
        #pragma unroll
        for (int na = 0; na < 2; na++) {
            int col = hh * 64 + wn * 16 + na * 8 + (lane & 3) * 2;
            float2 r0 = { o[am][na][0] * inv0, o[am][na][1] * inv0 };
            float2 r1 = { o[am][na][2] * inv1, o[am][na][3] * inv1 };
            *(float2*)&y[tok0 * DIMN + col] = r0;
            *(float2*)&y[(tok0 + 8) * DIMN + col] = r1;
        }
    }
}

// ---------------- elementwise kernels ----------------
__global__ void embed_kernel(const int* __restrict__ tokens,
                             const float* __restrict__ embed,
                             float* __restrict__ h)
{
    int row = blockIdx.x;
    int tok = tokens[row];
    ((float4*)(h + (long)row * DIMN))[threadIdx.x] =
        ((const float4*)(embed + (long)tok * DIMN))[threadIdx.x];
}

__global__ void rmsnorm_kernel(const float* __restrict__ x,
                               const float* __restrict__ w,
                               float* __restrict__ out)
{
    int row = blockIdx.x;
    float4 v = ((const float4*)(x + (long)row * DIMN))[threadIdx.x];
    float ss = v.x*v.x + v.y*v.y + v.z*v.z + v.w*v.w;
    __shared__ float red[8];
    #pragma unroll
    for (int o = 16; o > 0; o >>= 1) ss += __shfl_xor_sync(0xFFFFFFFFu, ss, o);
    if ((threadIdx.x & 31) == 0) red[threadIdx.x >> 5] = ss;
    __syncthreads();
    if (threadIdx.x < 8) {
        float s = red[threadIdx.x];
        #pragma unroll
        for (int o = 4; o > 0; o >>= 1) s += __shfl_xor_sync(0xFFu, s, o);
        if (threadIdx.x == 0) red[0] = s;
    }
    __syncthreads();
    float scale = rsqrtf(red[0] * (1.0f / DIMN) + EPS);
    float4 wv = ((const float4*)w)[threadIdx.x];
    float4 o4 = { v.x*scale*wv.x, v.y*scale*wv.y, v.z*scale*wv.z, v.w*scale*wv.w };
    ((float4*)(out + (long)row * DIMN))[threadIdx.x] = o4;
}

__global__ void silu_mul_kernel(float4* __restrict__ g, const float4* __restrict__ u)
{
    long i = (long)blockIdx.x * blockDim.x + threadIdx.x;
    float4 gv = g[i], uv = u[i];
    gv.x = gv.x / (1.0f + __expf(-gv.x)) * uv.x;
    gv.y = gv.y / (1.0f + __expf(-gv.y)) * uv.y;
    gv.z = gv.z / (1.0f + __expf(-gv.z)) * uv.z;
    gv.w = gv.w / (1.0f + __expf(-gv.w)) * uv.w;
    g[i] = gv;
}

// vt[(b*H+h)][d][s] = v[b*SEQ+s][h*64+d]
__global__ void transpose_v_kernel(const float* __restrict__ v, float* __restrict__ vt)
{
    __shared__ float t[32][33];
    int bh = blockIdx.z, b = bh >> 4, hh = bh & 15;
    int s0 = blockIdx.x * 32, d0 = blockIdx.y * 32;
    int tx = threadIdx.x, ty = threadIdx.y;    // 32 x 8
    #pragma unroll
    for (int j = 0; j < 32; j += 8)
        t[ty + j][tx] = v[(long)(b * SEQ + s0 + ty + j) * DIMN + hh * HEAD_DIM + d0 + tx];
    __syncthreads();
    #pragma unroll
    for (int j = 0; j < 32; j += 8)
        vt[((long)bh * HEAD_DIM + d0 + ty + j) * SEQ + s0 + tx] = t[tx][ty + j];
}

// ---------------- launcher ----------------
extern "C" void kernel_launch(void* const* d_in, const int* in_sizes, int n_in,
                              void* d_out, int out_size)
{
    const int*   tokens  = (const int*)  d_in[0];
    const float* embed   = (const float*)d_in[1];
    const float* Wq      = (const float*)d_in[2];
    const float* Wk      = (const float*)d_in[3];
    const float* Wv      = (const float*)d_in[4];
    const float* Wo      = (const float*)d_in[5];
    const float* Wg      = (const float*)d_in[6];
    const float* Wu      = (const float*)d_in[7];
    const float* Wd      = (const float*)d_in[8];
    const float* ln1     = (const float*)d_in[9];
    const float* ln2     = (const float*)d_in[10];
    const float* norm_w  = (const float*)d_in[11];
    const float* lm_head = (const float*)d_in[12];
    float* out = (float*)d_out;

    float *h, *x, *q, *k, *v, *vt, *y, *gate, *up;
    cudaGetSymbolAddress((void**)&h,    g_h);
    cudaGetSymbolAddress((void**)&x,    g_x);
    cudaGetSymbolAddress((void**)&q,    g_q);
    cudaGetSymbolAddress((void**)&k,    g_k);
    cudaGetSymbolAddress((void**)&v,    g_v);
    cudaGetSymbolAddress((void**)&vt,   g_vt);
    cudaGetSymbolAddress((void**)&y,    g_y);
    cudaGetSymbolAddress((void**)&gate, g_gate);
    cudaGetSymbolAddress((void**)&up,   g_up);

    const int DYN128 = 2 * (16384 + 128 * 128);   // 65536
    cudaFuncSetAttribute(mma_gemm<128, false>, cudaFuncAttributeMaxDynamicSharedMemorySize, DYN128);
    cudaFuncSetAttribute(mma_gemm<128, true>,  cudaFuncAttributeMaxDynamicSharedMemorySize, DYN128);
    cudaFuncSetAttribute(mma_gemm_multi<128>,  cudaFuncAttributeMaxDynamicSharedMemorySize, DYN128);
    cudaFuncSetAttribute(flash_attn, cudaFuncAttributeMaxDynamicSharedMemorySize, FA_BYTES);

    embed_kernel<<<MTOK, 256>>>(tokens, embed, h);

    dim3 gQKV  (MTOK / 128, DIMN / 128, 3);
    dim3 gGU   (MTOK / 128, HIDDEN / 128, 2);
    dim3 gProj (MTOK / 128, DIMN / 128, 1);
    dim3 gHead (MTOK / 128, VOCAB / 128, 1);
    dim3 gFa   (SEQ / 128, 1, BATCH * HEADS);
    dim3 gTr   (SEQ / 32, HEAD_DIM / 32, BATCH * HEADS);

    for (int l = 0; l < LAYERS; l++) {
        const float* wq = Wq + (long)l * DIMN * DIMN;
        const float* wk = Wk + (long)l * DIMN * DIMN;
        const float* wv = Wv + (long)l * DIMN * DIMN;
        const float* wo = Wo + (long)l * DIMN * DIMN;
        const float* wg = Wg + (long)l * HIDDEN * DIMN;
        const float* wu = Wu + (long)l * HIDDEN * DIMN;
        const float* wd = Wd + (long)l * DIMN * HIDDEN;

        rmsnorm_kernel<<<MTOK, 256>>>(h, ln1 + (long)l * DIMN, x);

        {
            P3 p = { wq, wk, wv, q, k, v };
            mma_gemm_multi<128><<<gQKV, 256, DYN128>>>(x, DIMN, p, DIMN, DIMN, DIMN, 1.0f);
        }

        transpose_v_kernel<<<gTr, dim3(32, 8)>>>(v, vt);
        flash_attn<<<gFa, 256, FA_BYTES>>>(q, k, vt, y);

        mma_gemm<128, true><<<gProj, 256, DYN128>>>(y, DIMN, wo, DIMN,
                                                    h, DIMN, DIMN, 1.0f);

        rmsnorm_kernel<<<MTOK, 256>>>(h, ln2 + (long)l * DIMN, x);

        {
            P3 p = { wg, wu, wu, gate, up, up };
            mma_gemm_multi<128><<<gGU, 256, DYN128>>>(x, DIMN, p, DIMN, HIDDEN, DIMN, 1.0f);
        }

        silu_mul_kernel<<<(MTOK * (long)HIDDEN / 4) / 256, 256>>>((float4*)gate, (const float4*)up);

        mma_gemm<128, true><<<gProj, 256, DYN128>>>(gate, HIDDEN, wd, HIDDEN,
                                                    h, DIMN, HIDDEN, 1.0f);
    }

    rmsnorm_kernel<<<MTOK, 256>>>(h, norm_w, x);
    mma_gemm<128, false><<<gHead, 256, DYN128>>>(x, DIMN, lm_head, DIMN,
                                                 out, VOCAB, DIMN, 1.0f);
}